// round 1
// baseline (speedup 1.0000x reference)
#include <cuda_runtime.h>

// Problem constants
#define M_TOT   16384          // 16 * 32 * 32 tiles
#define NAB     36
#define CIN     64
#define COUT    64

// Scratch (allocation-free rule: __device__ globals)
__device__ float g_V[NAB * CIN * M_TOT];    // V[ab][ci][m]
__device__ float g_M[NAB * COUT * M_TOT];   // M[ab][co][m]
__device__ float g_Wt[NAB * CIN * COUT];    // Wt[ab][ci][co]

// ---------------------------------------------------------------------------
// K1: weight transpose  weight[co][ci][a][b] -> Wt[ab][ci][co]
// ---------------------------------------------------------------------------
__global__ __launch_bounds__(256) void wt_kernel(const float* __restrict__ w) {
    int idx = blockIdx.x * 256 + threadIdx.x;      // = (ab*64+ci)*64+co
    if (idx >= NAB * CIN * COUT) return;
    int co = idx & 63;
    int ci = (idx >> 6) & 63;
    int ab = idx >> 12;
    g_Wt[idx] = w[(co * 64 + ci) * 36 + ab];
}

// ---------------------------------------------------------------------------
// K2: input transform.  One thread per (ci, m) tile: V = BT * d * BT^T
// ---------------------------------------------------------------------------
__global__ __launch_bounds__(256) void in_transform(const float* __restrict__ x) {
    int idx = blockIdx.x * 256 + threadIdx.x;      // ci*16384 + m
    int m  = idx & 16383;
    int ci = idx >> 14;
    int n  = m >> 10;
    int p  = (m >> 5) & 31;
    int q  = m & 31;

    const float* xb = x + ((size_t)(n * 64 + ci)) * 128 * 128;
    int h0 = p * 4 - 1;
    int w0 = q * 4 - 1;

    float d[6][6];
#pragma unroll
    for (int i = 0; i < 6; i++) {
        int h = h0 + i;
        bool hv = ((unsigned)h < 128u);
        const float* xr = xb + h * 128;
#pragma unroll
        for (int j = 0; j < 6; j++) {
            int wj = w0 + j;
            d[i][j] = (hv && ((unsigned)wj < 128u)) ? xr[wj] : 0.0f;
        }
    }

    // t = BT * d   (along i)
    float t[6][6];
#pragma unroll
    for (int j = 0; j < 6; j++) {
        t[0][j] =  4.0f * d[0][j] - 5.0f * d[2][j] + d[4][j];
        t[1][j] = -4.0f * d[1][j] - 4.0f * d[2][j] + d[3][j] + d[4][j];
        t[2][j] =  4.0f * d[1][j] - 4.0f * d[2][j] - d[3][j] + d[4][j];
        t[3][j] = -2.0f * d[1][j] - 1.0f * d[2][j] + 2.0f * d[3][j] + d[4][j];
        t[4][j] =  2.0f * d[1][j] - 1.0f * d[2][j] - 2.0f * d[3][j] + d[4][j];
        t[5][j] =  4.0f * d[1][j] - 5.0f * d[3][j] + d[5][j];
    }

    // v[a][b] = sum_j BT[b][j] * t[a][j]; write to V[ab][ci][m]
    float* vout = g_V + (size_t)ci * M_TOT + m;
    const size_t plane = (size_t)CIN * M_TOT;
#pragma unroll
    for (int a = 0; a < 6; a++) {
        float v0 =  4.0f * t[a][0] - 5.0f * t[a][2] + t[a][4];
        float v1 = -4.0f * t[a][1] - 4.0f * t[a][2] + t[a][3] + t[a][4];
        float v2 =  4.0f * t[a][1] - 4.0f * t[a][2] - t[a][3] + t[a][4];
        float v3 = -2.0f * t[a][1] - 1.0f * t[a][2] + 2.0f * t[a][3] + t[a][4];
        float v4 =  2.0f * t[a][1] - 1.0f * t[a][2] - 2.0f * t[a][3] + t[a][4];
        float v5 =  4.0f * t[a][1] - 5.0f * t[a][3] + t[a][5];
        vout[(a * 6 + 0) * plane] = v0;
        vout[(a * 6 + 1) * plane] = v1;
        vout[(a * 6 + 2) * plane] = v2;
        vout[(a * 6 + 3) * plane] = v3;
        vout[(a * 6 + 4) * plane] = v4;
        vout[(a * 6 + 5) * plane] = v5;
    }
}

// ---------------------------------------------------------------------------
// K3: 36 batched GEMMs  M[ab][co][m] = sum_ci Wt[ab][ci][co] * V[ab][ci][m]
// CTA: 128 m x 64 co, K=64.  128 threads, 8x8 register tile (1B LDS / FMA).
// grid = (128 m-blocks, 6 ab-groups of 6)
// ---------------------------------------------------------------------------
__global__ __launch_bounds__(128) void gemm_kernel() {
    __shared__ float V_s[64][128];   // [ci][m]  32KB
    __shared__ float W_s[64][64];    // [ci][co] 16KB   total = 48KB exactly

    int tid = threadIdx.x;
    int mg  = tid & 15;     // m-group: 16 groups of 8
    int cog = tid >> 4;     // co-group: 8 groups of 8
    int m0  = blockIdx.x * 128;

    for (int abk = 0; abk < 6; abk++) {
        int ab = blockIdx.y * 6 + abk;
        __syncthreads();   // protect smem from previous iteration's readers

        // Load V tile: 64 rows x 128 floats = 2048 float4
        const float* vbase = g_V + (size_t)(ab * 64) * M_TOT + m0;
#pragma unroll
        for (int r = 0; r < 16; r++) {
            int t4 = r * 128 + tid;       // 0..2047
            int ci = t4 >> 5;             // 32 float4 per row
            int c4 = t4 & 31;
            float4 v = *(const float4*)(vbase + (size_t)ci * M_TOT + c4 * 4);
            *(float4*)&V_s[ci][c4 * 4] = v;
        }
        // Load W tile: 64 x 64 = 1024 float4
        const float* wbase = g_Wt + (ab * 64) * 64;
#pragma unroll
        for (int r = 0; r < 8; r++) {
            int t4 = r * 128 + tid;       // 0..1023
            int ci = t4 >> 4;
            int c4 = t4 & 15;
            float4 v = *(const float4*)(wbase + ci * 64 + c4 * 4);
            *(float4*)&W_s[ci][c4 * 4] = v;
        }
        __syncthreads();

        float acc[8][8];
#pragma unroll
        for (int i = 0; i < 8; i++)
#pragma unroll
            for (int j = 0; j < 8; j++) acc[i][j] = 0.0f;

#pragma unroll 4
        for (int ci = 0; ci < 64; ci++) {
            float4 va = *(const float4*)&V_s[ci][mg * 8];
            float4 vb = *(const float4*)&V_s[ci][mg * 8 + 4];
            float4 wa = *(const float4*)&W_s[ci][cog * 8];
            float4 wb = *(const float4*)&W_s[ci][cog * 8 + 4];
            float vm[8] = {va.x, va.y, va.z, va.w, vb.x, vb.y, vb.z, vb.w};
            float wn[8] = {wa.x, wa.y, wa.z, wa.w, wb.x, wb.y, wb.z, wb.w};
#pragma unroll
            for (int i = 0; i < 8; i++)
#pragma unroll
                for (int j = 0; j < 8; j++)
                    acc[i][j] += vm[i] * wn[j];
        }

        // Store M[ab][co][m]
        float* mbase = g_M + (size_t)(ab * 64) * M_TOT + m0 + mg * 8;
#pragma unroll
        for (int j = 0; j < 8; j++) {
            int co = cog * 8 + j;
            float* mrow = mbase + (size_t)co * M_TOT;
            *(float4*)(mrow)     = make_float4(acc[0][j], acc[1][j], acc[2][j], acc[3][j]);
            *(float4*)(mrow + 4) = make_float4(acc[4][j], acc[5][j], acc[6][j], acc[7][j]);
        }
    }
}

// ---------------------------------------------------------------------------
// K4: output transform  Y = AT * M * AT^T + bias, scatter to NCHW
// One thread per (co, m).
// ---------------------------------------------------------------------------
__global__ __launch_bounds__(256) void out_transform(const float* __restrict__ bias,
                                                     float* __restrict__ y) {
    int idx = blockIdx.x * 256 + threadIdx.x;     // co*16384 + m
    int m  = idx & 16383;
    int co = idx >> 14;

    float Mv[6][6];
    const float* msrc = g_M + (size_t)co * M_TOT + m;
    const size_t plane = (size_t)COUT * M_TOT;
#pragma unroll
    for (int a = 0; a < 6; a++)
#pragma unroll
        for (int b = 0; b < 6; b++)
            Mv[a][b] = msrc[(a * 6 + b) * plane];

    // P[x][b] = sum_a AT[x][a] * M[a][b]
    float P[4][6];
#pragma unroll
    for (int b = 0; b < 6; b++) {
        P[0][b] = Mv[0][b] + Mv[1][b] + Mv[2][b] + Mv[3][b] + Mv[4][b];
        P[1][b] = Mv[1][b] - Mv[2][b] + 2.0f * Mv[3][b] - 2.0f * Mv[4][b];
        P[2][b] = Mv[1][b] + Mv[2][b] + 4.0f * Mv[3][b] + 4.0f * Mv[4][b];
        P[3][b] = Mv[1][b] - Mv[2][b] + 8.0f * Mv[3][b] - 8.0f * Mv[4][b] + Mv[5][b];
    }

    float bv = bias[co];
    int n = m >> 10;
    int p = (m >> 5) & 31;
    int q = m & 31;
    float* yb = y + (((size_t)(n * 64 + co)) * 128 + p * 4) * 128 + q * 4;

#pragma unroll
    for (int xr = 0; xr < 4; xr++) {
        float y0 = P[xr][0] + P[xr][1] + P[xr][2] + P[xr][3] + P[xr][4] + bv;
        float y1 = P[xr][1] - P[xr][2] + 2.0f * P[xr][3] - 2.0f * P[xr][4] + bv;
        float y2 = P[xr][1] + P[xr][2] + 4.0f * P[xr][3] + 4.0f * P[xr][4] + bv;
        float y3 = P[xr][1] - P[xr][2] + 8.0f * P[xr][3] - 8.0f * P[xr][4] + P[xr][5] + bv;
        *(float4*)(yb + xr * 128) = make_float4(y0, y1, y2, y3);
    }
}

// ---------------------------------------------------------------------------
extern "C" void kernel_launch(void* const* d_in, const int* in_sizes, int n_in,
                              void* d_out, int out_size) {
    const float* x = (const float*)d_in[0];   // (16, 64, 128, 128) f32
    const float* w = (const float*)d_in[1];   // (64, 64, 6, 6) f32
    const float* b = (const float*)d_in[2];   // (64,) f32
    float* y = (float*)d_out;                 // (16, 64, 128, 128) f32

    wt_kernel<<<(NAB * CIN * COUT + 255) / 256, 256>>>(w);
    in_transform<<<(CIN * M_TOT) / 256, 256>>>(x);
    gemm_kernel<<<dim3(M_TOT / 128, 6), 128>>>();
    out_transform<<<(COUT * M_TOT) / 256, 256>>>(b, y);
}

// round 2
// speedup vs baseline: 1.0506x; 1.0506x over previous
#include <cuda_runtime.h>

// Problem constants
#define M_TOT   16384          // 16 * 32 * 32 tiles
#define NAB     36
#define CIN     64
#define COUT    64

typedef unsigned long long ull;

// Scratch (allocation-free rule: __device__ globals)
__device__ float g_V[NAB * CIN * M_TOT];    // V[ab][ci][m]
__device__ float g_M[NAB * COUT * M_TOT];   // M[ab][co][m]
__device__ float g_Wt[NAB * CIN * COUT];    // Wt[ab][ci][co]

// ---- packed fp32x2 helpers (Blackwell-only PTX; ptxas never auto-fuses) ----
__device__ __forceinline__ ull pack2(float x) {
    ull r;
    asm("mov.b64 %0, {%1, %1};" : "=l"(r) : "f"(x));
    return r;
}
__device__ __forceinline__ void ffma2(ull& d, ull a, ull b) {
    asm("fma.rn.f32x2 %0, %1, %2, %0;" : "+l"(d) : "l"(a), "l"(b));
}

// ---------------------------------------------------------------------------
// K1: weight transpose  weight[co][ci][a][b] -> Wt[ab][ci][co]
// ---------------------------------------------------------------------------
__global__ __launch_bounds__(256) void wt_kernel(const float* __restrict__ w) {
    int idx = blockIdx.x * 256 + threadIdx.x;      // = (ab*64+ci)*64+co
    if (idx >= NAB * CIN * COUT) return;
    int co = idx & 63;
    int ci = (idx >> 6) & 63;
    int ab = idx >> 12;
    g_Wt[idx] = w[(co * 64 + ci) * 36 + ab];
}

// ---------------------------------------------------------------------------
// K2: input transform.  One thread per (ci, m) tile: V = BT * d * BT^T
// ---------------------------------------------------------------------------
__global__ __launch_bounds__(256) void in_transform(const float* __restrict__ x) {
    int idx = blockIdx.x * 256 + threadIdx.x;      // ci*16384 + m
    int m  = idx & 16383;
    int ci = idx >> 14;
    int n  = m >> 10;
    int p  = (m >> 5) & 31;
    int q  = m & 31;

    const float* xb = x + ((size_t)(n * 64 + ci)) * 128 * 128;
    int h0 = p * 4 - 1;
    int w0 = q * 4 - 1;

    float d[6][6];
#pragma unroll
    for (int i = 0; i < 6; i++) {
        int h = h0 + i;
        bool hv = ((unsigned)h < 128u);
        const float* xr = xb + h * 128;
#pragma unroll
        for (int j = 0; j < 6; j++) {
            int wj = w0 + j;
            d[i][j] = (hv && ((unsigned)wj < 128u)) ? xr[wj] : 0.0f;
        }
    }

    // t = BT * d   (along i)
    float t[6][6];
#pragma unroll
    for (int j = 0; j < 6; j++) {
        t[0][j] =  4.0f * d[0][j] - 5.0f * d[2][j] + d[4][j];
        t[1][j] = -4.0f * d[1][j] - 4.0f * d[2][j] + d[3][j] + d[4][j];
        t[2][j] =  4.0f * d[1][j] - 4.0f * d[2][j] - d[3][j] + d[4][j];
        t[3][j] = -2.0f * d[1][j] - 1.0f * d[2][j] + 2.0f * d[3][j] + d[4][j];
        t[4][j] =  2.0f * d[1][j] - 1.0f * d[2][j] - 2.0f * d[3][j] + d[4][j];
        t[5][j] =  4.0f * d[1][j] - 5.0f * d[3][j] + d[5][j];
    }

    // v[a][b] = sum_j BT[b][j] * t[a][j]; write to V[ab][ci][m]
    float* vout = g_V + (size_t)ci * M_TOT + m;
    const size_t plane = (size_t)CIN * M_TOT;
#pragma unroll
    for (int a = 0; a < 6; a++) {
        float v0 =  4.0f * t[a][0] - 5.0f * t[a][2] + t[a][4];
        float v1 = -4.0f * t[a][1] - 4.0f * t[a][2] + t[a][3] + t[a][4];
        float v2 =  4.0f * t[a][1] - 4.0f * t[a][2] - t[a][3] + t[a][4];
        float v3 = -2.0f * t[a][1] - 1.0f * t[a][2] + 2.0f * t[a][3] + t[a][4];
        float v4 =  2.0f * t[a][1] - 1.0f * t[a][2] - 2.0f * t[a][3] + t[a][4];
        float v5 =  4.0f * t[a][1] - 5.0f * t[a][3] + t[a][5];
        vout[(a * 6 + 0) * plane] = v0;
        vout[(a * 6 + 1) * plane] = v1;
        vout[(a * 6 + 2) * plane] = v2;
        vout[(a * 6 + 3) * plane] = v3;
        vout[(a * 6 + 4) * plane] = v4;
        vout[(a * 6 + 5) * plane] = v5;
    }
}

// ---------------------------------------------------------------------------
// K3: 36 batched GEMMs  M[ab][co][m] = sum_ci Wt[ab][ci][co] * V[ab][ci][m]
// CTA: 128 m x 64 co, K=64.  128 threads, 8x8 register tile implemented as
// 4 (m-pair) x 8 (co) packed f32x2 accumulators -> 128 lane-FMA/cyc/SM.
// grid = (128 m-blocks, 6 ab-groups of 6)
// ---------------------------------------------------------------------------
__global__ __launch_bounds__(128) void gemm_kernel() {
    __shared__ float V_s[64][128];   // [ci][m]  32KB
    __shared__ float W_s[64][64];    // [ci][co] 16KB   total = 48KB

    int tid = threadIdx.x;
    int mg  = tid & 15;     // m-group: 16 groups of 8
    int cog = tid >> 4;     // co-group: 8 groups of 8
    int m0  = blockIdx.x * 128;

    for (int abk = 0; abk < 6; abk++) {
        int ab = blockIdx.y * 6 + abk;
        __syncthreads();   // protect smem from previous iteration's readers

        // Load V tile: 64 rows x 128 floats = 2048 float4
        const float* vbase = g_V + (size_t)(ab * 64) * M_TOT + m0;
#pragma unroll
        for (int r = 0; r < 16; r++) {
            int t4 = r * 128 + tid;       // 0..2047
            int ci = t4 >> 5;             // 32 float4 per row
            int c4 = t4 & 31;
            float4 v = *(const float4*)(vbase + (size_t)ci * M_TOT + c4 * 4);
            *(float4*)&V_s[ci][c4 * 4] = v;
        }
        // Load W tile: 64 x 64 = 1024 float4
        const float* wbase = g_Wt + (ab * 64) * 64;
#pragma unroll
        for (int r = 0; r < 8; r++) {
            int t4 = r * 128 + tid;       // 0..1023
            int ci = t4 >> 4;
            int c4 = t4 & 15;
            float4 v = *(const float4*)(wbase + ci * 64 + c4 * 4);
            *(float4*)&W_s[ci][c4 * 4] = v;
        }
        __syncthreads();

        // acc2[ip][j]: m-pair ip covers rows (2ip, 2ip+1), co column j
        ull acc2[4][8];
#pragma unroll
        for (int i = 0; i < 4; i++)
#pragma unroll
            for (int j = 0; j < 8; j++) acc2[i][j] = 0ULL;

#pragma unroll 8
        for (int ci = 0; ci < 64; ci++) {
            // V: 8 m-values = 4 packed pairs, via two 16B LDS
            ulonglong2 vA = *(const ulonglong2*)&V_s[ci][mg * 8];
            ulonglong2 vB = *(const ulonglong2*)&V_s[ci][mg * 8 + 4];
            ull vm[4] = {vA.x, vA.y, vB.x, vB.y};

            // W: 8 co-values, broadcast-packed (w,w)
            float4 wa = *(const float4*)&W_s[ci][cog * 8];
            float4 wb = *(const float4*)&W_s[ci][cog * 8 + 4];
            ull wp[8];
            wp[0] = pack2(wa.x); wp[1] = pack2(wa.y);
            wp[2] = pack2(wa.z); wp[3] = pack2(wa.w);
            wp[4] = pack2(wb.x); wp[5] = pack2(wb.y);
            wp[6] = pack2(wb.z); wp[7] = pack2(wb.w);

#pragma unroll
            for (int j = 0; j < 8; j++)
#pragma unroll
                for (int i = 0; i < 4; i++)
                    ffma2(acc2[i][j], vm[i], wp[j]);
        }

        // Store M[ab][co][m]: acc2 pairs are exactly (m,m+1) memory order
        float* mbase = g_M + (size_t)(ab * 64) * M_TOT + m0 + mg * 8;
#pragma unroll
        for (int j = 0; j < 8; j++) {
            int co = cog * 8 + j;
            float* mrow = mbase + (size_t)co * M_TOT;
            *(ulonglong2*)(mrow)     = make_ulonglong2(acc2[0][j], acc2[1][j]);
            *(ulonglong2*)(mrow + 4) = make_ulonglong2(acc2[2][j], acc2[3][j]);
        }
    }
}

// ---------------------------------------------------------------------------
// K4: output transform  Y = AT * M * AT^T + bias, scatter to NCHW
// One thread per (co, m).
// ---------------------------------------------------------------------------
__global__ __launch_bounds__(256) void out_transform(const float* __restrict__ bias,
                                                     float* __restrict__ y) {
    int idx = blockIdx.x * 256 + threadIdx.x;     // co*16384 + m
    int m  = idx & 16383;
    int co = idx >> 14;

    float Mv[6][6];
    const float* msrc = g_M + (size_t)co * M_TOT + m;
    const size_t plane = (size_t)COUT * M_TOT;
#pragma unroll
    for (int a = 0; a < 6; a++)
#pragma unroll
        for (int b = 0; b < 6; b++)
            Mv[a][b] = msrc[(a * 6 + b) * plane];

    // P[x][b] = sum_a AT[x][a] * M[a][b]
    float P[4][6];
#pragma unroll
    for (int b = 0; b < 6; b++) {
        P[0][b] = Mv[0][b] + Mv[1][b] + Mv[2][b] + Mv[3][b] + Mv[4][b];
        P[1][b] = Mv[1][b] - Mv[2][b] + 2.0f * Mv[3][b] - 2.0f * Mv[4][b];
        P[2][b] = Mv[1][b] + Mv[2][b] + 4.0f * Mv[3][b] + 4.0f * Mv[4][b];
        P[3][b] = Mv[1][b] - Mv[2][b] + 8.0f * Mv[3][b] - 8.0f * Mv[4][b] + Mv[5][b];
    }

    float bv = bias[co];
    int n = m >> 10;
    int p = (m >> 5) & 31;
    int q = m & 31;
    float* yb = y + (((size_t)(n * 64 + co)) * 128 + p * 4) * 128 + q * 4;

#pragma unroll
    for (int xr = 0; xr < 4; xr++) {
        float y0 = P[xr][0] + P[xr][1] + P[xr][2] + P[xr][3] + P[xr][4] + bv;
        float y1 = P[xr][1] - P[xr][2] + 2.0f * P[xr][3] - 2.0f * P[xr][4] + bv;
        float y2 = P[xr][1] + P[xr][2] + 4.0f * P[xr][3] + 4.0f * P[xr][4] + bv;
        float y3 = P[xr][1] - P[xr][2] + 8.0f * P[xr][3] - 8.0f * P[xr][4] + P[xr][5] + bv;
        *(float4*)(yb + xr * 128) = make_float4(y0, y1, y2, y3);
    }
}

// ---------------------------------------------------------------------------
extern "C" void kernel_launch(void* const* d_in, const int* in_sizes, int n_in,
                              void* d_out, int out_size) {
    const float* x = (const float*)d_in[0];   // (16, 64, 128, 128) f32
    const float* w = (const float*)d_in[1];   // (64, 64, 6, 6) f32
    const float* b = (const float*)d_in[2];   // (64,) f32
    float* y = (float*)d_out;                 // (16, 64, 128, 128) f32

    wt_kernel<<<(NAB * CIN * COUT + 255) / 256, 256>>>(w);
    in_transform<<<(CIN * M_TOT) / 256, 256>>>(x);
    gemm_kernel<<<dim3(M_TOT / 128, 6), 128>>>();
    out_transform<<<(COUT * M_TOT) / 256, 256>>>(b, y);
}